// round 5
// baseline (speedup 1.0000x reference)
#include <cuda_runtime.h>

// Problem dims (compile-time, from reference)
#define BDIM 2
#define CDIM 3
#define DDIM 128
#define HDIM 192
#define WDIM 192

// ---------------------------------------------------------------------------
// Fused X+Y pass. One block per (b,c,d) slice: the full H x W slab lives in
// a padded smem tile (PADW=193 -> row-walk AND column-walk conflict-free).
// X solve: thread t = row h, walk w. Y solve: thread t = column w, walk h.
// Global traffic: one read + one write of the volume.
// ---------------------------------------------------------------------------
constexpr int PADW    = 193;
constexpr int XYTPB   = 256;
constexpr int SMEM_XY = (HDIM * PADW + 6 * 192) * (int)sizeof(float);

__global__ __launch_bounds__(XYTPB) void fused_xy_kernel(
    const float* __restrict__ in, float* __restrict__ out,
    const float* __restrict__ ax, const float* __restrict__ bx,
    const float* __restrict__ cx,
    const float* __restrict__ ay, const float* __restrict__ by,
    const float* __restrict__ cy)
{
    extern __shared__ float smem[];
    float* tile    = smem;                       // [HDIM][PADW]
    float* x_inva  = tile + HDIM * PADW;         // [192]
    float* x_binva = x_inva + 192;               // b[i]*inva[i]
    float* x_c     = x_binva + 192;
    float* y_inva  = x_c + 192;
    float* y_binva = y_inva + 192;
    float* y_c     = y_binva + 192;

    const int t = threadIdx.x;

    for (int i = t; i < WDIM; i += XYTPB) {
        const float ivx = 1.0f / ax[i];
        const float ivy = 1.0f / ay[i];
        x_inva[i] = ivx;  y_inva[i] = ivy;
        x_binva[i] = (i < WDIM - 1) ? bx[i] * ivx : 0.0f;
        y_binva[i] = (i < HDIM - 1) ? by[i] * ivy : 0.0f;
        x_c[i] = (i < WDIM - 1) ? cx[i] : 0.0f;
        y_c[i] = (i < HDIM - 1) ? cy[i] : 0.0f;
    }

    // --- stage slice in: lane -> (4 rows x 8 col-quads): LDG.128 coalesced,
    //     scalar STS hits 32 distinct banks (bank = h + 4*wq mod 32).
    const size_t sbase = (size_t)blockIdx.x * (HDIM * WDIM);
    const int hl  = t >> 3;        // 0..31
    const int wq0 = t & 7;         // 0..7
    #pragma unroll
    for (int hp = 0; hp < 6; hp++) {
        const int h = hp * 32 + hl;
        #pragma unroll
        for (int k = 0; k < 6; k++) {
            const int wq = wq0 + 8 * k;
            float4 v = *(const float4*)(in + sbase + (size_t)h * WDIM + wq * 4);
            float* d = tile + h * PADW + wq * 4;
            d[0] = v.x; d[1] = v.y; d[2] = v.z; d[3] = v.w;
        }
    }
    __syncthreads();

    // --- X solve: thread t = row t, walk w (addr t*193+i -> conflict-free)
    if (t < HDIM) {
        float* ln = tile + t * PADW;
        float carry = ln[0];
        #pragma unroll 8
        for (int i = 1; i < WDIM; i++) {
            carry = fmaf(-x_c[i - 1], carry, ln[i]);
            ln[i] = carry;
        }
        carry *= x_inva[WDIM - 1];
        ln[WDIM - 1] = carry;
        #pragma unroll 8
        for (int i = WDIM - 2; i >= 0; i--) {
            carry = fmaf(-x_binva[i], carry, ln[i] * x_inva[i]);
            ln[i] = carry;
        }
    }
    __syncthreads();

    // --- Y solve: thread t = column t, walk h (addr i*193+t -> conflict-free)
    if (t < WDIM) {
        float* cl = tile + t;
        float carry = cl[0];
        #pragma unroll 8
        for (int i = 1; i < HDIM; i++) {
            carry = fmaf(-y_c[i - 1], carry, cl[(size_t)i * PADW]);
            cl[(size_t)i * PADW] = carry;
        }
        carry *= y_inva[HDIM - 1];
        cl[(size_t)(HDIM - 1) * PADW] = carry;
        #pragma unroll 8
        for (int i = HDIM - 2; i >= 0; i--) {
            carry = fmaf(-y_binva[i], carry, cl[(size_t)i * PADW] * y_inva[i]);
            cl[(size_t)i * PADW] = carry;
        }
    }
    __syncthreads();

    // --- stage slice out (mirror of load)
    #pragma unroll
    for (int hp = 0; hp < 6; hp++) {
        const int h = hp * 32 + hl;
        #pragma unroll
        for (int k = 0; k < 6; k++) {
            const int wq = wq0 + 8 * k;
            const float* s = tile + h * PADW + wq * 4;
            float4 v = make_float4(s[0], s[1], s[2], s[3]);
            *(float4*)(out + sbase + (size_t)h * WDIM + wq * 4) = v;
        }
    }
}

// ---------------------------------------------------------------------------
// Z pass: solve along D (stride H*W), float4-vectorized over w. In-place
// two-sweep Thomas; forward y lives in d_out, backward reads hit L2
// (block working set ~512KB). binva trick keeps the serial chain at 1 FMA.
// ---------------------------------------------------------------------------
constexpr int ZTPB = 256;

__global__ __launch_bounds__(ZTPB) void solve_z_kernel(
    float* __restrict__ data,
    const float* __restrict__ a, const float* __restrict__ b,
    const float* __restrict__ c)
{
    __shared__ float s_inva[DDIM], s_binva[DDIM], s_c[DDIM];
    const int t = threadIdx.x;
    for (int i = t; i < DDIM; i += ZTPB) {
        const float iv = 1.0f / a[i];
        s_inva[i] = iv;
        s_binva[i] = (i < DDIM - 1) ? b[i] * iv : 0.0f;
        s_c[i]     = (i < DDIM - 1) ? c[i] : 0.0f;
    }
    __syncthreads();

    constexpr int PL = HDIM * WDIM / 4;          // float4s per d-plane (per bc)
    const int L  = blockIdx.x * ZTPB + t;        // float4 line over (b,c)x(h,w4)
    const int bc = L / PL;
    const int hw = L - bc * PL;
    float4* p = (float4*)data + (size_t)bc * (DDIM * PL) + hw;

    float4 carry = p[0];
    #pragma unroll 4
    for (int i = 1; i < DDIM; i++) {
        const float4 x = p[(size_t)i * PL];
        const float ci = s_c[i - 1];
        carry.x = fmaf(-ci, carry.x, x.x);
        carry.y = fmaf(-ci, carry.y, x.y);
        carry.z = fmaf(-ci, carry.z, x.z);
        carry.w = fmaf(-ci, carry.w, x.w);
        p[(size_t)i * PL] = carry;
    }
    const float ian = s_inva[DDIM - 1];
    carry.x *= ian; carry.y *= ian; carry.z *= ian; carry.w *= ian;
    p[(size_t)(DDIM - 1) * PL] = carry;
    #pragma unroll 4
    for (int i = DDIM - 2; i >= 0; i--) {
        const float4 y = p[(size_t)i * PL];
        const float bi = s_binva[i], iai = s_inva[i];
        carry.x = fmaf(-bi, carry.x, y.x * iai);
        carry.y = fmaf(-bi, carry.y, y.y * iai);
        carry.z = fmaf(-bi, carry.z, y.z * iai);
        carry.w = fmaf(-bi, carry.w, y.w * iai);
        p[(size_t)i * PL] = carry;
    }
}

// ---------------------------------------------------------------------------
// Launch
// ---------------------------------------------------------------------------
extern "C" void kernel_launch(void* const* d_in, const int* in_sizes, int n_in,
                              void* d_out, int out_size)
{
    const float* field = (const float*)d_in[0];
    const float* ax = (const float*)d_in[1];
    const float* bx = (const float*)d_in[2];
    const float* cx = (const float*)d_in[3];
    const float* ay = (const float*)d_in[4];
    const float* by = (const float*)d_in[5];
    const float* cy = (const float*)d_in[6];
    const float* az = (const float*)d_in[7];
    const float* bz = (const float*)d_in[8];
    const float* cz = (const float*)d_in[9];
    float* out = (float*)d_out;

    (void)in_sizes; (void)n_in; (void)out_size;

    // Opt-in to large dynamic smem (graph-capture-safe: enqueues no work).
    cudaFuncSetAttribute(fused_xy_kernel,
                         cudaFuncAttributeMaxDynamicSharedMemorySize, SMEM_XY);

    // Fused X+Y: one block per (b,c,d) slice = 2*3*128 = 768 blocks
    fused_xy_kernel<<<BDIM * CDIM * DDIM, XYTPB, SMEM_XY>>>(
        field, out, ax, bx, cx, ay, by, cy);

    // Z: float4 lines = 2*3*192*48 = 55296 / 256 = 216 blocks
    const int l4_z = BDIM * CDIM * HDIM * (WDIM / 4);
    solve_z_kernel<<<l4_z / ZTPB, ZTPB>>>(out, az, bz, cz);
}

// round 6
// speedup vs baseline: 1.0967x; 1.0967x over previous
#include <cuda_runtime.h>

// Problem dims (compile-time, from reference)
#define BDIM 2
#define CDIM 3
#define DDIM 128
#define HDIM 192
#define WDIM 192

constexpr int NWARPS = 8;
constexpr int TPB    = NWARPS * 32;

// ---------------------------------------------------------------------------
// X pass (proven R4 kernel): solve along W (contiguous). Warp-local 32x33
// transpose tiles, 6 chunks of 32 columns; y intermediates round-trip through
// `out` (L2-resident), last chunk kept in registers.
// ---------------------------------------------------------------------------
__global__ __launch_bounds__(TPB) void solve_x_kernel(
    const float* __restrict__ in, float* __restrict__ out,
    const float* __restrict__ a, const float* __restrict__ b,
    const float* __restrict__ c)
{
    __shared__ float tile[NWARPS][32][33];
    __shared__ float s_inva[WDIM], s_b[WDIM], s_c[WDIM];

    const int t    = threadIdx.x;
    const int wid  = t >> 5;
    const int lane = t & 31;

    for (int i = t; i < WDIM; i += TPB) {
        s_inva[i] = 1.0f / a[i];
        if (i < WDIM - 1) { s_b[i] = b[i]; s_c[i] = c[i]; }
    }
    __syncthreads();

    float (*tl)[33] = tile[wid];
    const int line0 = (blockIdx.x * NWARPS + wid) * 32;
    const int r0 = lane >> 3;
    const int cm = (lane & 7) * 4;

    float carry = 0.0f;
    float yreg[32];

    // forward sweep
    for (int k = 0; k < 6; k++) {
        const int c0 = k * 32;
        #pragma unroll
        for (int rr = 0; rr < 32; rr += 4) {
            const int r = rr + r0;
            float4 v = *(const float4*)(in + (size_t)(line0 + r) * WDIM + c0 + cm);
            tl[r][cm]     = v.x; tl[r][cm + 1] = v.y;
            tl[r][cm + 2] = v.z; tl[r][cm + 3] = v.w;
        }
        __syncwarp();
        #pragma unroll
        for (int j = 0; j < 32; j++) {
            const float x = tl[lane][j];
            const int i = c0 + j;
            carry = (i == 0) ? x : fmaf(-s_c[i - 1], carry, x);
            yreg[j] = carry;
        }
        if (k < 5) {
            #pragma unroll
            for (int j = 0; j < 32; j++) tl[lane][j] = yreg[j];
            __syncwarp();
            #pragma unroll
            for (int rr = 0; rr < 32; rr += 4) {
                const int r = rr + r0;
                float4 v = make_float4(tl[r][cm], tl[r][cm + 1],
                                       tl[r][cm + 2], tl[r][cm + 3]);
                *(float4*)(out + (size_t)(line0 + r) * WDIM + c0 + cm) = v;
            }
        }
        __syncwarp();
    }

    // backward sweep: chunk 5 from registers
    {
        const int c0 = 5 * 32;
        #pragma unroll
        for (int j = 31; j >= 0; j--) {
            const int i = c0 + j;
            const float x = yreg[j];
            carry = (i == WDIM - 1) ? x * s_inva[i]
                                    : fmaf(-s_b[i], carry, x) * s_inva[i];
            yreg[j] = carry;
        }
        #pragma unroll
        for (int j = 0; j < 32; j++) tl[lane][j] = yreg[j];
        __syncwarp();
        #pragma unroll
        for (int rr = 0; rr < 32; rr += 4) {
            const int r = rr + r0;
            float4 v = make_float4(tl[r][cm], tl[r][cm + 1],
                                   tl[r][cm + 2], tl[r][cm + 3]);
            *(float4*)(out + (size_t)(line0 + r) * WDIM + c0 + cm) = v;
        }
        __syncwarp();
    }
    for (int k = 4; k >= 0; k--) {
        const int c0 = k * 32;
        #pragma unroll
        for (int rr = 0; rr < 32; rr += 4) {
            const int r = rr + r0;
            float4 v = *(const float4*)(out + (size_t)(line0 + r) * WDIM + c0 + cm);
            tl[r][cm]     = v.x; tl[r][cm + 1] = v.y;
            tl[r][cm + 2] = v.z; tl[r][cm + 3] = v.w;
        }
        __syncwarp();
        #pragma unroll
        for (int j = 31; j >= 0; j--) {
            const int i = c0 + j;
            carry = fmaf(-s_b[i], carry, tl[lane][j]) * s_inva[i];
            yreg[j] = carry;
        }
        #pragma unroll
        for (int j = 0; j < 32; j++) tl[lane][j] = yreg[j];
        __syncwarp();
        #pragma unroll
        for (int rr = 0; rr < 32; rr += 4) {
            const int r = rr + r0;
            float4 v = make_float4(tl[r][cm], tl[r][cm + 1],
                                   tl[r][cm + 2], tl[r][cm + 3]);
            *(float4*)(out + (size_t)(line0 + r) * WDIM + c0 + cm) = v;
        }
        __syncwarp();
    }
}

// ---------------------------------------------------------------------------
// Strided passes, same warp-transpose pattern. Warp owns 32 consecutive-w
// lines; element (line=lane, step=s) at base + s*STRIDE + lane. Stage
// 32(step)x32(line) subtiles: float4 loads along w, solve walks tile columns
// tl[j][lane] (banks (j+lane)%32 -> conflict-free). y round-trip via global
// (<=16KB/warp -> cache-resident); last chunk in registers. In-place.
// ---------------------------------------------------------------------------
template <int N, int STRIDE>
__device__ __forceinline__ void warp_strided_solve(
    float* __restrict__ base, float (*__restrict__ tl)[33], int lane,
    const float* __restrict__ s_inva, const float* __restrict__ s_binva,
    const float* __restrict__ s_c)
{
    constexpr int NC = N / 32;
    const int r0 = lane >> 3;
    const int cm = (lane & 7) * 4;

    float carry = 0.0f;
    float yreg[32];

    // forward sweep
    #pragma unroll
    for (int k = 0; k < NC; k++) {
        const int s0 = k * 32;
        #pragma unroll
        for (int rr = 0; rr < 32; rr += 4) {
            const int r = rr + r0;
            float4 v = *(const float4*)(base + (size_t)(s0 + r) * STRIDE + cm);
            tl[r][cm]     = v.x; tl[r][cm + 1] = v.y;
            tl[r][cm + 2] = v.z; tl[r][cm + 3] = v.w;
        }
        __syncwarp();
        #pragma unroll
        for (int j = 0; j < 32; j++) {
            const float x = tl[j][lane];
            const int i = s0 + j;
            carry = (i == 0) ? x : fmaf(-s_c[i - 1], carry, x);
            yreg[j] = carry;
        }
        if (k < NC - 1) {
            #pragma unroll
            for (int j = 0; j < 32; j++) tl[j][lane] = yreg[j];
            __syncwarp();
            #pragma unroll
            for (int rr = 0; rr < 32; rr += 4) {
                const int r = rr + r0;
                float4 v = make_float4(tl[r][cm], tl[r][cm + 1],
                                       tl[r][cm + 2], tl[r][cm + 3]);
                *(float4*)(base + (size_t)(s0 + r) * STRIDE + cm) = v;
            }
        }
        __syncwarp();
    }

    // backward sweep: last chunk from registers (binva[N-1]==0 unifies i=N-1)
    {
        const int s0 = (NC - 1) * 32;
        #pragma unroll
        for (int j = 31; j >= 0; j--) {
            const int i = s0 + j;
            carry = fmaf(-s_binva[i], carry, yreg[j] * s_inva[i]);
            yreg[j] = carry;
        }
        #pragma unroll
        for (int j = 0; j < 32; j++) tl[j][lane] = yreg[j];
        __syncwarp();
        #pragma unroll
        for (int rr = 0; rr < 32; rr += 4) {
            const int r = rr + r0;
            float4 v = make_float4(tl[r][cm], tl[r][cm + 1],
                                   tl[r][cm + 2], tl[r][cm + 3]);
            *(float4*)(base + (size_t)(s0 + r) * STRIDE + cm) = v;
        }
        __syncwarp();
    }
    #pragma unroll
    for (int k = NC - 2; k >= 0; k--) {
        const int s0 = k * 32;
        #pragma unroll
        for (int rr = 0; rr < 32; rr += 4) {
            const int r = rr + r0;
            float4 v = *(const float4*)(base + (size_t)(s0 + r) * STRIDE + cm);
            tl[r][cm]     = v.x; tl[r][cm + 1] = v.y;
            tl[r][cm + 2] = v.z; tl[r][cm + 3] = v.w;
        }
        __syncwarp();
        #pragma unroll
        for (int j = 31; j >= 0; j--) {
            const int i = s0 + j;
            carry = fmaf(-s_binva[i], carry, tl[j][lane] * s_inva[i]);
            yreg[j] = carry;
        }
        #pragma unroll
        for (int j = 0; j < 32; j++) tl[j][lane] = yreg[j];
        __syncwarp();
        #pragma unroll
        for (int rr = 0; rr < 32; rr += 4) {
            const int r = rr + r0;
            float4 v = make_float4(tl[r][cm], tl[r][cm + 1],
                                   tl[r][cm + 2], tl[r][cm + 3]);
            *(float4*)(base + (size_t)(s0 + r) * STRIDE + cm) = v;
        }
        __syncwarp();
    }
}

template <int N>
__device__ __forceinline__ void load_coeffs(
    const float* __restrict__ a, const float* __restrict__ b,
    const float* __restrict__ c,
    float* __restrict__ s_inva, float* __restrict__ s_binva,
    float* __restrict__ s_c, int t)
{
    for (int i = t; i < N; i += TPB) {
        const float iv = 1.0f / a[i];
        s_inva[i]  = iv;
        s_binva[i] = (i < N - 1) ? b[i] * iv : 0.0f;
        s_c[i]     = (i < N - 1) ? c[i] : 0.0f;
    }
}

__global__ __launch_bounds__(TPB) void solve_y_kernel(
    float* __restrict__ data,
    const float* __restrict__ a, const float* __restrict__ b,
    const float* __restrict__ c)
{
    __shared__ float tile[NWARPS][32][33];
    __shared__ float s_inva[HDIM], s_binva[HDIM], s_c[HDIM];
    const int t = threadIdx.x, wid = t >> 5, lane = t & 31;
    load_coeffs<HDIM>(a, b, c, s_inva, s_binva, s_c, t);
    __syncthreads();

    const int task = blockIdx.x * NWARPS + wid;   // over (b,c,d) x wchunk
    const int bcd  = task / (WDIM / 32);
    const int wc   = task - bcd * (WDIM / 32);
    float* base = data + (size_t)bcd * (HDIM * WDIM) + wc * 32;
    warp_strided_solve<HDIM, WDIM>(base, tile[wid], lane, s_inva, s_binva, s_c);
}

__global__ __launch_bounds__(TPB) void solve_z_kernel(
    float* __restrict__ data,
    const float* __restrict__ a, const float* __restrict__ b,
    const float* __restrict__ c)
{
    __shared__ float tile[NWARPS][32][33];
    __shared__ float s_inva[DDIM], s_binva[DDIM], s_c[DDIM];
    const int t = threadIdx.x, wid = t >> 5, lane = t & 31;
    load_coeffs<DDIM>(a, b, c, s_inva, s_binva, s_c, t);
    __syncthreads();

    const int task = blockIdx.x * NWARPS + wid;   // over (b,c,h) x wchunk
    const int bch  = task / (WDIM / 32);
    const int wc   = task - bch * (WDIM / 32);
    const int bc   = bch / HDIM;
    const int h    = bch - bc * HDIM;
    float* base = data + (size_t)bc * (DDIM * HDIM * WDIM)
                       + (size_t)h * WDIM + wc * 32;
    warp_strided_solve<DDIM, HDIM * WDIM>(base, tile[wid], lane,
                                          s_inva, s_binva, s_c);
}

// ---------------------------------------------------------------------------
// Launch
// ---------------------------------------------------------------------------
extern "C" void kernel_launch(void* const* d_in, const int* in_sizes, int n_in,
                              void* d_out, int out_size)
{
    const float* field = (const float*)d_in[0];
    const float* ax = (const float*)d_in[1];
    const float* bx = (const float*)d_in[2];
    const float* cx = (const float*)d_in[3];
    const float* ay = (const float*)d_in[4];
    const float* by = (const float*)d_in[5];
    const float* cy = (const float*)d_in[6];
    const float* az = (const float*)d_in[7];
    const float* bz = (const float*)d_in[8];
    const float* cz = (const float*)d_in[9];
    float* out = (float*)d_out;

    (void)in_sizes; (void)n_in; (void)out_size;

    // X: 147456 lines / 256 = 576 blocks
    const int lines_x = BDIM * CDIM * DDIM * HDIM;
    solve_x_kernel<<<lines_x / (NWARPS * 32), TPB>>>(field, out, ax, bx, cx);

    // Y: warp tasks = (b*c*d) * (W/32) = 768*6 = 4608 / 8 = 576 blocks
    const int tasks_y = BDIM * CDIM * DDIM * (WDIM / 32);
    solve_y_kernel<<<tasks_y / NWARPS, TPB>>>(out, ay, by, cy);

    // Z: warp tasks = (b*c*h) * (W/32) = 1152*6 = 6912 / 8 = 864 blocks
    const int tasks_z = BDIM * CDIM * HDIM * (WDIM / 32);
    solve_z_kernel<<<tasks_z / NWARPS, TPB>>>(out, az, bz, cz);
}

// round 7
// speedup vs baseline: 1.3936x; 1.2708x over previous
#include <cuda_runtime.h>

// Problem dims (compile-time, from reference)
#define BDIM 2
#define CDIM 3
#define DDIM 128
#define HDIM 192
#define WDIM 192

// ---------------------------------------------------------------------------
// X pass (proven R4 kernel, unchanged): solve along W (contiguous).
// Warp-local 32x33 transpose tiles, 6 chunks of 32 columns; y intermediates
// round-trip through `out` (L2-resident), last chunk kept in registers.
// ---------------------------------------------------------------------------
constexpr int XWARPS = 8;
constexpr int XTPB   = XWARPS * 32;

__global__ __launch_bounds__(XTPB) void solve_x_kernel(
    const float* __restrict__ in, float* __restrict__ out,
    const float* __restrict__ a, const float* __restrict__ b,
    const float* __restrict__ c)
{
    __shared__ float tile[XWARPS][32][33];
    __shared__ float s_inva[WDIM], s_b[WDIM], s_c[WDIM];

    const int t    = threadIdx.x;
    const int wid  = t >> 5;
    const int lane = t & 31;

    for (int i = t; i < WDIM; i += XTPB) {
        s_inva[i] = 1.0f / a[i];
        if (i < WDIM - 1) { s_b[i] = b[i]; s_c[i] = c[i]; }
    }
    __syncthreads();

    float (*tl)[33] = tile[wid];
    const int line0 = (blockIdx.x * XWARPS + wid) * 32;
    const int r0 = lane >> 3;
    const int cm = (lane & 7) * 4;

    float carry = 0.0f;
    float yreg[32];

    // forward sweep
    for (int k = 0; k < 6; k++) {
        const int c0 = k * 32;
        #pragma unroll
        for (int rr = 0; rr < 32; rr += 4) {
            const int r = rr + r0;
            float4 v = *(const float4*)(in + (size_t)(line0 + r) * WDIM + c0 + cm);
            tl[r][cm]     = v.x; tl[r][cm + 1] = v.y;
            tl[r][cm + 2] = v.z; tl[r][cm + 3] = v.w;
        }
        __syncwarp();
        #pragma unroll
        for (int j = 0; j < 32; j++) {
            const float x = tl[lane][j];
            const int i = c0 + j;
            carry = (i == 0) ? x : fmaf(-s_c[i - 1], carry, x);
            yreg[j] = carry;
        }
        if (k < 5) {
            #pragma unroll
            for (int j = 0; j < 32; j++) tl[lane][j] = yreg[j];
            __syncwarp();
            #pragma unroll
            for (int rr = 0; rr < 32; rr += 4) {
                const int r = rr + r0;
                float4 v = make_float4(tl[r][cm], tl[r][cm + 1],
                                       tl[r][cm + 2], tl[r][cm + 3]);
                *(float4*)(out + (size_t)(line0 + r) * WDIM + c0 + cm) = v;
            }
        }
        __syncwarp();
    }

    // backward sweep: chunk 5 from registers
    {
        const int c0 = 5 * 32;
        #pragma unroll
        for (int j = 31; j >= 0; j--) {
            const int i = c0 + j;
            const float x = yreg[j];
            carry = (i == WDIM - 1) ? x * s_inva[i]
                                    : fmaf(-s_b[i], carry, x) * s_inva[i];
            yreg[j] = carry;
        }
        #pragma unroll
        for (int j = 0; j < 32; j++) tl[lane][j] = yreg[j];
        __syncwarp();
        #pragma unroll
        for (int rr = 0; rr < 32; rr += 4) {
            const int r = rr + r0;
            float4 v = make_float4(tl[r][cm], tl[r][cm + 1],
                                   tl[r][cm + 2], tl[r][cm + 3]);
            *(float4*)(out + (size_t)(line0 + r) * WDIM + c0 + cm) = v;
        }
        __syncwarp();
    }
    for (int k = 4; k >= 0; k--) {
        const int c0 = k * 32;
        #pragma unroll
        for (int rr = 0; rr < 32; rr += 4) {
            const int r = rr + r0;
            float4 v = *(const float4*)(out + (size_t)(line0 + r) * WDIM + c0 + cm);
            tl[r][cm]     = v.x; tl[r][cm + 1] = v.y;
            tl[r][cm + 2] = v.z; tl[r][cm + 3] = v.w;
        }
        __syncwarp();
        #pragma unroll
        for (int j = 31; j >= 0; j--) {
            const int i = c0 + j;
            carry = fmaf(-s_b[i], carry, tl[lane][j]) * s_inva[i];
            yreg[j] = carry;
        }
        #pragma unroll
        for (int j = 0; j < 32; j++) tl[lane][j] = yreg[j];
        __syncwarp();
        #pragma unroll
        for (int rr = 0; rr < 32; rr += 4) {
            const int r = rr + r0;
            float4 v = make_float4(tl[r][cm], tl[r][cm + 1],
                                   tl[r][cm + 2], tl[r][cm + 3]);
            *(float4*)(out + (size_t)(line0 + r) * WDIM + c0 + cm) = v;
        }
        __syncwarp();
    }
}

// ---------------------------------------------------------------------------
// Strided passes: scalar thread-per-line (coalesced across w), forward
// intermediates y held in REGISTERS for the last HOLD steps; only the first
// N-HOLD steps round-trip through global (written then re-read -> L2 hot).
// Fully unrolled -> compile-time register indexing + deep load MLP.
// ---------------------------------------------------------------------------
template <int N, int HOLD, int STRIDE>
__device__ __forceinline__ void solve_line_reg(
    float* __restrict__ p,
    const float* __restrict__ s_inva,
    const float* __restrict__ s_binva,
    const float* __restrict__ s_c)
{
    constexpr int SPILL = N - HOLD;   // steps whose y round-trips via global
    float yreg[HOLD];
    float carry;

    // forward sweep
    carry = p[0];
    if (SPILL > 0) p[0] = carry; else yreg[0] = carry;
    #pragma unroll
    for (int i = 1; i < N; i++) {
        carry = fmaf(-s_c[i - 1], carry, p[(size_t)i * STRIDE]);
        if (i < SPILL) p[(size_t)i * STRIDE] = carry;
        else           yreg[i - SPILL] = carry;
    }

    // backward sweep: register-held region (binva[N-1]==0 unifies i==N-1)
    carry = 0.0f;
    #pragma unroll
    for (int i = N - 1; i >= SPILL; i--) {
        carry = fmaf(-s_binva[i], carry, yreg[i - SPILL] * s_inva[i]);
        p[(size_t)i * STRIDE] = carry;
    }
    // spilled region: reload y from global (L2-hot)
    #pragma unroll
    for (int i = SPILL - 1; i >= 0; i--) {
        carry = fmaf(-s_binva[i], carry, p[(size_t)i * STRIDE] * s_inva[i]);
        p[(size_t)i * STRIDE] = carry;
    }
}

constexpr int STPB = 256;

template <int N>
__device__ __forceinline__ void load_coeffs_s(
    const float* __restrict__ a, const float* __restrict__ b,
    const float* __restrict__ c,
    float* __restrict__ s_inva, float* __restrict__ s_binva,
    float* __restrict__ s_c)
{
    for (int i = threadIdx.x; i < N; i += STPB) {
        const float iv = 1.0f / a[i];
        s_inva[i]  = iv;
        s_binva[i] = (i < N - 1) ? b[i] * iv : 0.0f;
        s_c[i]     = (i < N - 1) ? c[i] : 0.0f;
    }
}

__global__ __launch_bounds__(STPB, 1) void solve_y_kernel(
    float* __restrict__ data,
    const float* __restrict__ a, const float* __restrict__ b,
    const float* __restrict__ c)
{
    __shared__ float s_inva[HDIM], s_binva[HDIM], s_c[HDIM];
    load_coeffs_s<HDIM>(a, b, c, s_inva, s_binva, s_c);
    __syncthreads();

    const int L   = blockIdx.x * STPB + threadIdx.x;  // line over (b,c,d) x w
    const int bcd = L / WDIM;
    const int w   = L - bcd * WDIM;
    float* p = data + (size_t)bcd * (HDIM * WDIM) + w;
    solve_line_reg<HDIM, 128, WDIM>(p, s_inva, s_binva, s_c);
}

__global__ __launch_bounds__(STPB, 1) void solve_z_kernel(
    float* __restrict__ data,
    const float* __restrict__ a, const float* __restrict__ b,
    const float* __restrict__ c)
{
    __shared__ float s_inva[DDIM], s_binva[DDIM], s_c[DDIM];
    load_coeffs_s<DDIM>(a, b, c, s_inva, s_binva, s_c);
    __syncthreads();

    const int L  = blockIdx.x * STPB + threadIdx.x;   // line over (b,c) x (h,w)
    const int bc = L / (HDIM * WDIM);
    const int hw = L - bc * (HDIM * WDIM);
    float* p = data + (size_t)bc * (DDIM * HDIM * WDIM) + hw;
    solve_line_reg<DDIM, DDIM, HDIM * WDIM>(p, s_inva, s_binva, s_c);
}

// ---------------------------------------------------------------------------
// Launch
// ---------------------------------------------------------------------------
extern "C" void kernel_launch(void* const* d_in, const int* in_sizes, int n_in,
                              void* d_out, int out_size)
{
    const float* field = (const float*)d_in[0];
    const float* ax = (const float*)d_in[1];
    const float* bx = (const float*)d_in[2];
    const float* cx = (const float*)d_in[3];
    const float* ay = (const float*)d_in[4];
    const float* by = (const float*)d_in[5];
    const float* cy = (const float*)d_in[6];
    const float* az = (const float*)d_in[7];
    const float* bz = (const float*)d_in[8];
    const float* cz = (const float*)d_in[9];
    float* out = (float*)d_out;

    (void)in_sizes; (void)n_in; (void)out_size;

    // X: 147456 lines / 256 = 576 blocks
    const int lines_x = BDIM * CDIM * DDIM * HDIM;
    solve_x_kernel<<<lines_x / (XWARPS * 32), XTPB>>>(field, out, ax, bx, cx);

    // Y: lines = b*c*d*w = 147456 / 256 = 576 blocks
    const int lines_y = BDIM * CDIM * DDIM * WDIM;
    solve_y_kernel<<<lines_y / STPB, STPB>>>(out, ay, by, cy);

    // Z: lines = b*c*h*w = 221184 / 256 = 864 blocks
    const int lines_z = BDIM * CDIM * HDIM * WDIM;
    solve_z_kernel<<<lines_z / STPB, STPB>>>(out, az, bz, cz);
}

// round 8
// speedup vs baseline: 1.4802x; 1.0621x over previous
#include <cuda_runtime.h>

// Problem dims (compile-time, from reference)
#define BDIM 2
#define CDIM 3
#define DDIM 128
#define HDIM 192
#define WDIM 192

// ---------------------------------------------------------------------------
// X pass: solve along W (contiguous). Warp-local 32x33 transpose tiles,
// 6 chunks of 32 columns; y intermediates round-trip through `out`
// (L2-resident), last chunk kept in registers.
// __launch_bounds__(256,4): force <=64 regs -> 4 blocks/SM, single wave.
// ---------------------------------------------------------------------------
constexpr int XWARPS = 8;
constexpr int XTPB   = XWARPS * 32;

__global__ __launch_bounds__(XTPB, 4) void solve_x_kernel(
    const float* __restrict__ in, float* __restrict__ out,
    const float* __restrict__ a, const float* __restrict__ b,
    const float* __restrict__ c)
{
    __shared__ float tile[XWARPS][32][33];
    __shared__ float s_inva[WDIM], s_b[WDIM], s_c[WDIM];

    const int t    = threadIdx.x;
    const int wid  = t >> 5;
    const int lane = t & 31;

    for (int i = t; i < WDIM; i += XTPB) {
        s_inva[i] = 1.0f / a[i];
        if (i < WDIM - 1) { s_b[i] = b[i]; s_c[i] = c[i]; }
    }
    __syncthreads();

    float (*tl)[33] = tile[wid];
    const int line0 = (blockIdx.x * XWARPS + wid) * 32;
    const int r0 = lane >> 3;
    const int cm = (lane & 7) * 4;

    float carry = 0.0f;
    float yreg[32];

    // forward sweep
    for (int k = 0; k < 6; k++) {
        const int c0 = k * 32;
        #pragma unroll
        for (int rr = 0; rr < 32; rr += 4) {
            const int r = rr + r0;
            float4 v = *(const float4*)(in + (size_t)(line0 + r) * WDIM + c0 + cm);
            tl[r][cm]     = v.x; tl[r][cm + 1] = v.y;
            tl[r][cm + 2] = v.z; tl[r][cm + 3] = v.w;
        }
        __syncwarp();
        #pragma unroll
        for (int j = 0; j < 32; j++) {
            const float x = tl[lane][j];
            const int i = c0 + j;
            carry = (i == 0) ? x : fmaf(-s_c[i - 1], carry, x);
            yreg[j] = carry;
        }
        if (k < 5) {
            #pragma unroll
            for (int j = 0; j < 32; j++) tl[lane][j] = yreg[j];
            __syncwarp();
            #pragma unroll
            for (int rr = 0; rr < 32; rr += 4) {
                const int r = rr + r0;
                float4 v = make_float4(tl[r][cm], tl[r][cm + 1],
                                       tl[r][cm + 2], tl[r][cm + 3]);
                *(float4*)(out + (size_t)(line0 + r) * WDIM + c0 + cm) = v;
            }
        }
        __syncwarp();
    }

    // backward sweep: chunk 5 from registers
    {
        const int c0 = 5 * 32;
        #pragma unroll
        for (int j = 31; j >= 0; j--) {
            const int i = c0 + j;
            const float x = yreg[j];
            carry = (i == WDIM - 1) ? x * s_inva[i]
                                    : fmaf(-s_b[i], carry, x) * s_inva[i];
            yreg[j] = carry;
        }
        #pragma unroll
        for (int j = 0; j < 32; j++) tl[lane][j] = yreg[j];
        __syncwarp();
        #pragma unroll
        for (int rr = 0; rr < 32; rr += 4) {
            const int r = rr + r0;
            float4 v = make_float4(tl[r][cm], tl[r][cm + 1],
                                   tl[r][cm + 2], tl[r][cm + 3]);
            *(float4*)(out + (size_t)(line0 + r) * WDIM + c0 + cm) = v;
        }
        __syncwarp();
    }
    for (int k = 4; k >= 0; k--) {
        const int c0 = k * 32;
        #pragma unroll
        for (int rr = 0; rr < 32; rr += 4) {
            const int r = rr + r0;
            float4 v = *(const float4*)(out + (size_t)(line0 + r) * WDIM + c0 + cm);
            tl[r][cm]     = v.x; tl[r][cm + 1] = v.y;
            tl[r][cm + 2] = v.z; tl[r][cm + 3] = v.w;
        }
        __syncwarp();
        #pragma unroll
        for (int j = 31; j >= 0; j--) {
            const int i = c0 + j;
            carry = fmaf(-s_b[i], carry, tl[lane][j]) * s_inva[i];
            yreg[j] = carry;
        }
        #pragma unroll
        for (int j = 0; j < 32; j++) tl[lane][j] = yreg[j];
        __syncwarp();
        #pragma unroll
        for (int rr = 0; rr < 32; rr += 4) {
            const int r = rr + r0;
            float4 v = make_float4(tl[r][cm], tl[r][cm + 1],
                                   tl[r][cm + 2], tl[r][cm + 3]);
            *(float4*)(out + (size_t)(line0 + r) * WDIM + c0 + cm) = v;
        }
        __syncwarp();
    }
}

// ---------------------------------------------------------------------------
// Strided passes: scalar thread-per-line (coalesced across w), forward
// intermediates y held in REGISTERS for the last HOLD steps; only the first
// N-HOLD steps round-trip through global (written then re-read -> L2 hot).
// 128-thread blocks: regs/block small enough for 3 blocks/SM co-residency.
// ---------------------------------------------------------------------------
template <int N, int HOLD, int STRIDE>
__device__ __forceinline__ void solve_line_reg(
    float* __restrict__ p,
    const float* __restrict__ s_inva,
    const float* __restrict__ s_binva,
    const float* __restrict__ s_c)
{
    constexpr int SPILL = N - HOLD;   // steps whose y round-trips via global
    float yreg[HOLD];
    float carry;

    // forward sweep
    carry = p[0];
    if (SPILL > 0) p[0] = carry; else yreg[0] = carry;
    #pragma unroll
    for (int i = 1; i < N; i++) {
        carry = fmaf(-s_c[i - 1], carry, p[(size_t)i * STRIDE]);
        if (i < SPILL) p[(size_t)i * STRIDE] = carry;
        else           yreg[i - SPILL] = carry;
    }

    // backward sweep: register-held region (binva[N-1]==0 unifies i==N-1)
    carry = 0.0f;
    #pragma unroll
    for (int i = N - 1; i >= SPILL; i--) {
        carry = fmaf(-s_binva[i], carry, yreg[i - SPILL] * s_inva[i]);
        p[(size_t)i * STRIDE] = carry;
    }
    // spilled region: reload y from global (L2-hot)
    #pragma unroll
    for (int i = SPILL - 1; i >= 0; i--) {
        carry = fmaf(-s_binva[i], carry, p[(size_t)i * STRIDE] * s_inva[i]);
        p[(size_t)i * STRIDE] = carry;
    }
}

constexpr int STPB = 128;

template <int N>
__device__ __forceinline__ void load_coeffs_s(
    const float* __restrict__ a, const float* __restrict__ b,
    const float* __restrict__ c,
    float* __restrict__ s_inva, float* __restrict__ s_binva,
    float* __restrict__ s_c)
{
    for (int i = threadIdx.x; i < N; i += STPB) {
        const float iv = 1.0f / a[i];
        s_inva[i]  = iv;
        s_binva[i] = (i < N - 1) ? b[i] * iv : 0.0f;
        s_c[i]     = (i < N - 1) ? c[i] : 0.0f;
    }
}

__global__ __launch_bounds__(STPB, 1) void solve_y_kernel(
    float* __restrict__ data,
    const float* __restrict__ a, const float* __restrict__ b,
    const float* __restrict__ c)
{
    __shared__ float s_inva[HDIM], s_binva[HDIM], s_c[HDIM];
    load_coeffs_s<HDIM>(a, b, c, s_inva, s_binva, s_c);
    __syncthreads();

    const int L   = blockIdx.x * STPB + threadIdx.x;  // line over (b,c,d) x w
    const int bcd = L / WDIM;
    const int w   = L - bcd * WDIM;
    float* p = data + (size_t)bcd * (HDIM * WDIM) + w;
    solve_line_reg<HDIM, 128, WDIM>(p, s_inva, s_binva, s_c);
}

__global__ __launch_bounds__(STPB, 1) void solve_z_kernel(
    float* __restrict__ data,
    const float* __restrict__ a, const float* __restrict__ b,
    const float* __restrict__ c)
{
    __shared__ float s_inva[DDIM], s_binva[DDIM], s_c[DDIM];
    load_coeffs_s<DDIM>(a, b, c, s_inva, s_binva, s_c);
    __syncthreads();

    const int L  = blockIdx.x * STPB + threadIdx.x;   // line over (b,c) x (h,w)
    const int bc = L / (HDIM * WDIM);
    const int hw = L - bc * (HDIM * WDIM);
    float* p = data + (size_t)bc * (DDIM * HDIM * WDIM) + hw;
    solve_line_reg<DDIM, DDIM, HDIM * WDIM>(p, s_inva, s_binva, s_c);
}

// ---------------------------------------------------------------------------
// Launch
// ---------------------------------------------------------------------------
extern "C" void kernel_launch(void* const* d_in, const int* in_sizes, int n_in,
                              void* d_out, int out_size)
{
    const float* field = (const float*)d_in[0];
    const float* ax = (const float*)d_in[1];
    const float* bx = (const float*)d_in[2];
    const float* cx = (const float*)d_in[3];
    const float* ay = (const float*)d_in[4];
    const float* by = (const float*)d_in[5];
    const float* cy = (const float*)d_in[6];
    const float* az = (const float*)d_in[7];
    const float* bz = (const float*)d_in[8];
    const float* cz = (const float*)d_in[9];
    float* out = (float*)d_out;

    (void)in_sizes; (void)n_in; (void)out_size;

    // X: 147456 lines / 256 = 576 blocks
    const int lines_x = BDIM * CDIM * DDIM * HDIM;
    solve_x_kernel<<<lines_x / (XWARPS * 32), XTPB>>>(field, out, ax, bx, cx);

    // Y: lines = b*c*d*w = 147456 / 128 = 1152 blocks
    const int lines_y = BDIM * CDIM * DDIM * WDIM;
    solve_y_kernel<<<lines_y / STPB, STPB>>>(out, ay, by, cy);

    // Z: lines = b*c*h*w = 221184 / 128 = 1728 blocks
    const int lines_z = BDIM * CDIM * HDIM * WDIM;
    solve_z_kernel<<<lines_z / STPB, STPB>>>(out, az, bz, cz);
}